// round 1
// baseline (speedup 1.0000x reference)
#include <cuda_runtime.h>
#include <cuda_bf16.h>
#include <math.h>

// Problem constants
#define BATCH 1024
#define NN 50
#define SS 50
#define HH 64
#define VOCAB 200000
#define VOUT 199999   // V-1 output columns

// Scratch for session embeddings a[B,H]
__device__ float g_a[BATCH * HH];

// ---------------------------------------------------------------------------
// Phase 1: per-session GGNN cell + attention readout -> g_a[b][0..63]
// One block per session, 256 threads, dynamic smem layout (floats):
//   sh   @ 0      (3200)  h / final reuse
//   sb1  @ 3200   (3200)  t_in  -> resetgate
//   sb2  @ 6400   (3200)  t_out -> inputgate
//   sb3  @ 9600   (3200)  input_in -> seq
//   sb4  @ 12800  (3200)  input_out -> attn vals
//   sb5  @ 16000  (3200)  h_new
//   sw   @ 19200  (12288) weight staging
//   sq1  @ 31488  (64)
//   salpha @ 31552 (64)
// total 31616 floats = 126464 bytes
#define SM1_FLOATS 31616

__device__ __forceinline__ float sigmoidf_(float x) {
    return 1.0f / (1.0f + expf(-x));
}

__global__ void __launch_bounds__(256, 1) session_kernel(
    const int* __restrict__ alias_inputs, const float* __restrict__ ain,
    const float* __restrict__ aou, const int* __restrict__ items,
    const int* __restrict__ mask, const float* __restrict__ emb,
    const float* __restrict__ einw, const float* __restrict__ einb,
    const float* __restrict__ eouw, const float* __restrict__ eoub,
    const float* __restrict__ biah, const float* __restrict__ boah,
    const float* __restrict__ igw, const float* __restrict__ igb,
    const float* __restrict__ hgw, const float* __restrict__ hgb,
    const float* __restrict__ fc1w, const float* __restrict__ fc1b,
    const float* __restrict__ fc2w, const float* __restrict__ fc2b,
    const float* __restrict__ fc3w)
{
    extern __shared__ float sm[];
    float* sh  = sm;
    float* sb1 = sm + 3200;
    float* sb2 = sm + 6400;
    float* sb3 = sm + 9600;
    float* sb4 = sm + 12800;
    float* sb5 = sm + 16000;
    float* sw  = sm + 19200;
    float* sq1 = sm + 31488;
    float* salpha = sm + 31552;
    __shared__ int s_last;

    const int b = blockIdx.x;
    const int tid = threadIdx.x;

    // Stage ein_w / eou_w (each 64x64) into sw[0..4095], sw[4096..8191]
    for (int e = tid; e < 4096; e += 256) {
        sw[e]        = einw[e];
        sw[4096 + e] = eouw[e];
    }
    // Gather h = emb[items]
    for (int e = tid; e < NN * HH; e += 256) {
        int n = e >> 6, c = e & 63;
        sh[e] = emb[(size_t)items[b * NN + n] * HH + c];
    }
    __syncthreads();

    // t1 = h @ ein_w + ein_b ; t2 = h @ eou_w + eou_b   (2-col microtile)
    for (int p = tid; p < NN * 32; p += 256) {
        int n = p >> 5, c = p & 31;
        float a1a = einb[c], a1b = einb[c + 32];
        float a2a = eoub[c], a2b = eoub[c + 32];
        const float* hr = sh + n * 64;
        #pragma unroll 8
        for (int k = 0; k < 64; k++) {
            float hv = hr[k];
            const float* w1 = sw + k * 64 + c;
            const float* w2 = sw + 4096 + k * 64 + c;
            a1a += hv * w1[0]; a1b += hv * w1[32];
            a2a += hv * w2[0]; a2b += hv * w2[32];
        }
        int e0 = n * 64 + c;
        sb1[e0] = a1a; sb1[e0 + 32] = a1b;
        sb2[e0] = a2a; sb2[e0 + 32] = a2b;
    }
    __syncthreads();

    // input_in = ain @ t1 + b_iah -> sb3 ; input_out = aou @ t2 + b_oah -> sb4
    for (int p = tid; p < NN * 32; p += 256) {
        int n = p >> 5, c = p & 31;
        float a1a = biah[c], a1b = biah[c + 32];
        float a2a = boah[c], a2b = boah[c + 32];
        const float* ar = ain + (size_t)b * (NN * NN) + n * NN;
        const float* br = aou + (size_t)b * (NN * NN) + n * NN;
        #pragma unroll 5
        for (int j = 0; j < NN; j++) {
            float av = ar[j], bv = br[j];
            const float* t1r = sb1 + j * 64 + c;
            const float* t2r = sb2 + j * 64 + c;
            a1a += av * t1r[0]; a1b += av * t1r[32];
            a2a += bv * t2r[0]; a2b += bv * t2r[32];
        }
        int e0 = n * 64 + c;
        sb3[e0] = a1a; sb3[e0 + 32] = a1b;
        sb4[e0] = a2a; sb4[e0 + 32] = a2b;
    }
    __syncthreads();

    // GRU gates, 3 column tiles of 64 (r, i, n)
    for (int g = 0; g < 3; g++) {
        // stage igate_w rows 0..127 col slice -> sw[0..8191],
        //       hgate_w rows 0..63  col slice -> sw[8192..12287]
        for (int e = tid; e < 8192; e += 256) {
            int k = e >> 6, c = e & 63;
            sw[e] = igw[k * 192 + g * 64 + c];
        }
        for (int e = tid; e < 4096; e += 256) {
            int k = e >> 6, c = e & 63;
            sw[8192 + e] = hgw[k * 192 + g * 64 + c];
        }
        __syncthreads();

        for (int p = tid; p < NN * 32; p += 256) {
            int n = p >> 5, c = p & 31;
            float sia = igb[g * 64 + c], sib = igb[g * 64 + c + 32];
            float sha = hgb[g * 64 + c], shb = hgb[g * 64 + c + 32];
            const float* r3 = sb3 + n * 64;
            const float* r4 = sb4 + n * 64;
            const float* hr = sh + n * 64;
            #pragma unroll 8
            for (int k = 0; k < 64; k++) {
                float v3 = r3[k], v4 = r4[k], vh = hr[k];
                const float* wi1 = sw + k * 64 + c;
                const float* wi2 = sw + (64 + k) * 64 + c;
                const float* wh  = sw + 8192 + k * 64 + c;
                sia += v3 * wi1[0];  sib += v3 * wi1[32];
                sia += v4 * wi2[0];  sib += v4 * wi2[32];
                sha += vh * wh[0];   shb += vh * wh[32];
            }
            int e0 = n * 64 + c, e1 = e0 + 32;
            if (g == 0) {
                sb1[e0] = sigmoidf_(sia + sha);
                sb1[e1] = sigmoidf_(sib + shb);
            } else if (g == 1) {
                sb2[e0] = sigmoidf_(sia + sha);
                sb2[e1] = sigmoidf_(sib + shb);
            } else {
                // newgate = tanh(i_n + r*h_n); h = ng + ig*(h - ng)
                float ng0 = tanhf(sia + sb1[e0] * sha);
                float ng1 = tanhf(sib + sb1[e1] * shb);
                sb5[e0] = ng0 + sb2[e0] * (sh[e0] - ng0);
                sb5[e1] = ng1 + sb2[e1] * (sh[e1] - ng1);
            }
        }
        __syncthreads();
    }

    // ---- attention readout, h_final = sb5 ----
    if (tid == 0) {
        int m = 0;
        for (int s = 0; s < SS; s++) m += mask[b * SS + s];
        s_last = m - 1;
    }
    // seq = h[alias] -> sb3 ; stage fc2_w -> sw[0..4095]
    for (int e = tid; e < SS * HH; e += 256) {
        int s = e >> 6, c = e & 63;
        sb3[e] = sb5[alias_inputs[b * SS + s] * 64 + c];
    }
    for (int e = tid; e < 4096; e += 256) sw[e] = fc2w[e];
    __syncthreads();

    // q1 = ht @ fc1_w + fc1_b
    if (tid < 64) {
        int c = tid;
        float q = fc1b[c];
        const float* htr = sb3 + s_last * 64;
        #pragma unroll 8
        for (int k = 0; k < 64; k++) q += htr[k] * fc1w[k * 64 + c];
        sq1[c] = q;
    }
    __syncthreads();

    // vals[s][c] = sigmoid(q1[c] + (seq@fc2+b)[s][c]) * fc3_w[c]  -> sb4
    for (int p = tid; p < SS * 32; p += 256) {
        int s = p >> 5, c = p & 31;
        float qa = fc2b[c], qb = fc2b[c + 32];
        const float* sr = sb3 + s * 64;
        #pragma unroll 8
        for (int k = 0; k < 64; k++) {
            float sv = sr[k];
            const float* w = sw + k * 64 + c;
            qa += sv * w[0]; qb += sv * w[32];
        }
        int e0 = s * 64 + c, e1 = e0 + 32;
        sb4[e0] = sigmoidf_(sq1[c] + qa) * fc3w[c];
        sb4[e1] = sigmoidf_(sq1[c + 32] + qb) * fc3w[c + 32];
    }
    __syncthreads();

    // alpha[s] = sum_c vals[s][c], masked
    if (tid < SS) {
        float al = 0.0f;
        #pragma unroll 8
        for (int c = 0; c < 64; c++) al += sb4[tid * 64 + c];
        salpha[tid] = al * (float)mask[b * SS + tid];
    }
    __syncthreads();

    // a[c] = sum_s alpha[s] * seq[s][c]
    if (tid < 64) {
        float a = 0.0f;
        #pragma unroll 5
        for (int s = 0; s < SS; s++) a += salpha[s] * sb3[s * 64 + tid];
        g_a[b * 64 + tid] = a;
    }
}

// ---------------------------------------------------------------------------
// Phase 2: out[b][v] = dot(a[b,:], emb[1+v,:])  -- fp32 with packed f32x2 FMA
// Block tile: 64 b x 128 v, 128 threads, per-thread 8b x 8v micro-tile.
// sA stores each a value DUPLICATED so ld.shared yields (a,a) packs directly.
#define PITCH 132                 // padded row pitch (floats), multiple of 4
#define SM2_BYTES (2 * 64 * PITCH * 4)

__device__ __forceinline__ unsigned long long ffma2(
    unsigned long long a, unsigned long long b, unsigned long long c)
{
    unsigned long long d;
    asm("fma.rn.f32x2 %0, %1, %2, %3;" : "=l"(d) : "l"(a), "l"(b), "l"(c));
    return d;
}
__device__ __forceinline__ float lo32(unsigned long long v) {
    return __uint_as_float((unsigned)v);
}
__device__ __forceinline__ float hi32(unsigned long long v) {
    return __uint_as_float((unsigned)(v >> 32));
}

__global__ void __launch_bounds__(128, 3) gemm_kernel(
    const float* __restrict__ emb, float* __restrict__ out)
{
    extern __shared__ float sm2[];
    float* sA = sm2;               // [k][2*bb dup], 64 x PITCH
    float* sE = sm2 + 64 * PITCH;  // [k][vv],       64 x PITCH

    const int btile = blockIdx.x;  // 0..15  (fast dim -> emb tile L2 reuse)
    const int vtile = blockIdx.y;  // 0..1562
    const int tid = threadIdx.x;
    const int b0 = btile * 64;
    const int v0 = vtile * 128;

    // Stage a tile duplicated: sA[k][2b] = sA[k][2b+1] = a[b0+b][k]
    for (int f = tid; f < 1024; f += 128) {
        int bb = f >> 4;
        int kq = (f & 15) * 4;
        float4 av = *(const float4*)&g_a[(b0 + bb) * 64 + kq];
        int o = 2 * bb;
        sA[(kq + 0) * PITCH + o] = av.x; sA[(kq + 0) * PITCH + o + 1] = av.x;
        sA[(kq + 1) * PITCH + o] = av.y; sA[(kq + 1) * PITCH + o + 1] = av.y;
        sA[(kq + 2) * PITCH + o] = av.z; sA[(kq + 2) * PITCH + o + 1] = av.z;
        sA[(kq + 3) * PITCH + o] = av.w; sA[(kq + 3) * PITCH + o + 1] = av.w;
    }
    // Stage emb tile transposed: sE[k][vv] = emb[1 + v0 + vv][k]
    for (int f = tid; f < 2048; f += 128) {
        int vv = f >> 4;
        int kq = (f & 15) * 4;
        float4 ev = make_float4(0.f, 0.f, 0.f, 0.f);
        if (v0 + vv < VOUT)
            ev = *(const float4*)&emb[(size_t)(1 + v0 + vv) * 64 + kq];
        sE[(kq + 0) * PITCH + vv] = ev.x;
        sE[(kq + 1) * PITCH + vv] = ev.y;
        sE[(kq + 2) * PITCH + vv] = ev.z;
        sE[(kq + 3) * PITCH + vv] = ev.w;
    }
    __syncthreads();

    const int j = tid & 15;        // v group -> v = v0 + j*8 ..
    const int i = tid >> 4;        // b group -> b = b0 + i*8 ..
    const int bb0 = i * 8;
    const int vv0 = j * 8;

    unsigned long long acc[8][4];
    #pragma unroll
    for (int x = 0; x < 8; x++)
        #pragma unroll
        for (int y = 0; y < 4; y++) acc[x][y] = 0ull;

    #pragma unroll 8
    for (int k = 0; k < 64; k++) {
        const ulonglong2* pa = (const ulonglong2*)&sA[k * PITCH + 2 * bb0];
        ulonglong2 a01 = pa[0];  // (b0,b0),(b1,b1)
        ulonglong2 a23 = pa[1];
        ulonglong2 a45 = pa[2];
        ulonglong2 a67 = pa[3];
        const ulonglong2* pe = (const ulonglong2*)&sE[k * PITCH + vv0];
        ulonglong2 e03 = pe[0];  // (v0,v1),(v2,v3)
        ulonglong2 e47 = pe[1];

        acc[0][0] = ffma2(a01.x, e03.x, acc[0][0]);
        acc[0][1] = ffma2(a01.x, e03.y, acc[0][1]);
        acc[0][2] = ffma2(a01.x, e47.x, acc[0][2]);
        acc[0][3] = ffma2(a01.x, e47.y, acc[0][3]);
        acc[1][0] = ffma2(a01.y, e03.x, acc[1][0]);
        acc[1][1] = ffma2(a01.y, e03.y, acc[1][1]);
        acc[1][2] = ffma2(a01.y, e47.x, acc[1][2]);
        acc[1][3] = ffma2(a01.y, e47.y, acc[1][3]);
        acc[2][0] = ffma2(a23.x, e03.x, acc[2][0]);
        acc[2][1] = ffma2(a23.x, e03.y, acc[2][1]);
        acc[2][2] = ffma2(a23.x, e47.x, acc[2][2]);
        acc[2][3] = ffma2(a23.x, e47.y, acc[2][3]);
        acc[3][0] = ffma2(a23.y, e03.x, acc[3][0]);
        acc[3][1] = ffma2(a23.y, e03.y, acc[3][1]);
        acc[3][2] = ffma2(a23.y, e47.x, acc[3][2]);
        acc[3][3] = ffma2(a23.y, e47.y, acc[3][3]);
        acc[4][0] = ffma2(a45.x, e03.x, acc[4][0]);
        acc[4][1] = ffma2(a45.x, e03.y, acc[4][1]);
        acc[4][2] = ffma2(a45.x, e47.x, acc[4][2]);
        acc[4][3] = ffma2(a45.x, e47.y, acc[4][3]);
        acc[5][0] = ffma2(a45.y, e03.x, acc[5][0]);
        acc[5][1] = ffma2(a45.y, e03.y, acc[5][1]);
        acc[5][2] = ffma2(a45.y, e47.x, acc[5][2]);
        acc[5][3] = ffma2(a45.y, e47.y, acc[5][3]);
        acc[6][0] = ffma2(a67.x, e03.x, acc[6][0]);
        acc[6][1] = ffma2(a67.x, e03.y, acc[6][1]);
        acc[6][2] = ffma2(a67.x, e47.x, acc[6][2]);
        acc[6][3] = ffma2(a67.x, e47.y, acc[6][3]);
        acc[7][0] = ffma2(a67.y, e03.x, acc[7][0]);
        acc[7][1] = ffma2(a67.y, e03.y, acc[7][1]);
        acc[7][2] = ffma2(a67.y, e47.x, acc[7][2]);
        acc[7][3] = ffma2(a67.y, e47.y, acc[7][3]);
    }

    // Epilogue: out rows are misaligned (VOUT odd) -> scalar stores of the
    // thread's 8 CONTIGUOUS v values per b row (L2 write-merges).
    const int vbase = v0 + vv0;
    #pragma unroll
    for (int bb = 0; bb < 8; bb++) {
        float r[8];
        #pragma unroll
        for (int vp = 0; vp < 4; vp++) {
            r[2 * vp]     = lo32(acc[bb][vp]);
            r[2 * vp + 1] = hi32(acc[bb][vp]);
        }
        float* orow = out + (size_t)(b0 + bb0 + bb) * VOUT + vbase;
        if (vbase + 8 <= VOUT) {
            #pragma unroll
            for (int q = 0; q < 8; q++) orow[q] = r[q];
        } else {
            #pragma unroll
            for (int q = 0; q < 8; q++)
                if (vbase + q < VOUT) orow[q] = r[q];
        }
    }
}

// ---------------------------------------------------------------------------
extern "C" void kernel_launch(void* const* d_in, const int* in_sizes, int n_in,
                              void* d_out, int out_size)
{
    const int*   alias_inputs = (const int*)  d_in[0];
    const float* ain   = (const float*)d_in[1];
    const float* aou   = (const float*)d_in[2];
    const int*   items = (const int*)  d_in[3];
    const int*   mask  = (const int*)  d_in[4];
    /* d_in[5] edge_index unused */
    const float* emb   = (const float*)d_in[6];
    const float* einw  = (const float*)d_in[7];
    const float* einb  = (const float*)d_in[8];
    const float* eouw  = (const float*)d_in[9];
    const float* eoub  = (const float*)d_in[10];
    const float* biah  = (const float*)d_in[11];
    const float* boah  = (const float*)d_in[12];
    const float* igw   = (const float*)d_in[13];
    const float* igb   = (const float*)d_in[14];
    const float* hgw   = (const float*)d_in[15];
    const float* hgb   = (const float*)d_in[16];
    const float* fc1w  = (const float*)d_in[17];
    const float* fc1b  = (const float*)d_in[18];
    const float* fc2w  = (const float*)d_in[19];
    const float* fc2b  = (const float*)d_in[20];
    const float* fc3w  = (const float*)d_in[21];
    float* out = (float*)d_out;

    cudaFuncSetAttribute(session_kernel,
                         cudaFuncAttributeMaxDynamicSharedMemorySize,
                         SM1_FLOATS * 4);
    cudaFuncSetAttribute(gemm_kernel,
                         cudaFuncAttributeMaxDynamicSharedMemorySize,
                         SM2_BYTES);

    session_kernel<<<BATCH, 256, SM1_FLOATS * 4>>>(
        alias_inputs, ain, aou, items, mask, emb,
        einw, einb, eouw, eoub, biah, boah,
        igw, igb, hgw, hgb, fc1w, fc1b, fc2w, fc2b, fc3w);

    dim3 grid(16, (VOUT + 127) / 128, 1);   // x = b-tile fast -> emb L2 reuse
    gemm_kernel<<<grid, 128, SM2_BYTES>>>(emb, out);
}

// round 3
// speedup vs baseline: 1.4431x; 1.4431x over previous
#include <cuda_runtime.h>
#include <cuda_bf16.h>
#include <math.h>
#include <stdint.h>

// Problem constants
#define BATCH 1024
#define NN 50
#define SS 50
#define HH 64
#define VOCAB 200000
#define VOUT 199999   // V-1 output columns

// Scratch for session embeddings a[B,H]
__device__ float g_a[BATCH * HH];

__device__ __forceinline__ float sigmoidf_(float x) {
    return 1.0f / (1.0f + expf(-x));
}

// ===========================================================================
// Phase 1: per-session GGNN cell + attention readout -> g_a  (unchanged)
// ===========================================================================
#define SM1_FLOATS 31616

__global__ void __launch_bounds__(256, 1) session_kernel(
    const int* __restrict__ alias_inputs, const float* __restrict__ ain,
    const float* __restrict__ aou, const int* __restrict__ items,
    const int* __restrict__ mask, const float* __restrict__ emb,
    const float* __restrict__ einw, const float* __restrict__ einb,
    const float* __restrict__ eouw, const float* __restrict__ eoub,
    const float* __restrict__ biah, const float* __restrict__ boah,
    const float* __restrict__ igw, const float* __restrict__ igb,
    const float* __restrict__ hgw, const float* __restrict__ hgb,
    const float* __restrict__ fc1w, const float* __restrict__ fc1b,
    const float* __restrict__ fc2w, const float* __restrict__ fc2b,
    const float* __restrict__ fc3w)
{
    extern __shared__ float sm[];
    float* sh  = sm;
    float* sb1 = sm + 3200;
    float* sb2 = sm + 6400;
    float* sb3 = sm + 9600;
    float* sb4 = sm + 12800;
    float* sb5 = sm + 16000;
    float* sw  = sm + 19200;
    float* sq1 = sm + 31488;
    float* salpha = sm + 31552;
    __shared__ int s_last;

    const int b = blockIdx.x;
    const int tid = threadIdx.x;

    for (int e = tid; e < 4096; e += 256) {
        sw[e]        = einw[e];
        sw[4096 + e] = eouw[e];
    }
    for (int e = tid; e < NN * HH; e += 256) {
        int n = e >> 6, c = e & 63;
        sh[e] = emb[(size_t)items[b * NN + n] * HH + c];
    }
    __syncthreads();

    for (int p = tid; p < NN * 32; p += 256) {
        int n = p >> 5, c = p & 31;
        float a1a = einb[c], a1b = einb[c + 32];
        float a2a = eoub[c], a2b = eoub[c + 32];
        const float* hr = sh + n * 64;
        #pragma unroll 8
        for (int k = 0; k < 64; k++) {
            float hv = hr[k];
            const float* w1 = sw + k * 64 + c;
            const float* w2 = sw + 4096 + k * 64 + c;
            a1a += hv * w1[0]; a1b += hv * w1[32];
            a2a += hv * w2[0]; a2b += hv * w2[32];
        }
        int e0 = n * 64 + c;
        sb1[e0] = a1a; sb1[e0 + 32] = a1b;
        sb2[e0] = a2a; sb2[e0 + 32] = a2b;
    }
    __syncthreads();

    for (int p = tid; p < NN * 32; p += 256) {
        int n = p >> 5, c = p & 31;
        float a1a = biah[c], a1b = biah[c + 32];
        float a2a = boah[c], a2b = boah[c + 32];
        const float* ar = ain + (size_t)b * (NN * NN) + n * NN;
        const float* br = aou + (size_t)b * (NN * NN) + n * NN;
        #pragma unroll 5
        for (int j = 0; j < NN; j++) {
            float av = ar[j], bv = br[j];
            const float* t1r = sb1 + j * 64 + c;
            const float* t2r = sb2 + j * 64 + c;
            a1a += av * t1r[0]; a1b += av * t1r[32];
            a2a += bv * t2r[0]; a2b += bv * t2r[32];
        }
        int e0 = n * 64 + c;
        sb3[e0] = a1a; sb3[e0 + 32] = a1b;
        sb4[e0] = a2a; sb4[e0 + 32] = a2b;
    }
    __syncthreads();

    for (int g = 0; g < 3; g++) {
        for (int e = tid; e < 8192; e += 256) {
            int k = e >> 6, c = e & 63;
            sw[e] = igw[k * 192 + g * 64 + c];
        }
        for (int e = tid; e < 4096; e += 256) {
            int k = e >> 6, c = e & 63;
            sw[8192 + e] = hgw[k * 192 + g * 64 + c];
        }
        __syncthreads();

        for (int p = tid; p < NN * 32; p += 256) {
            int n = p >> 5, c = p & 31;
            float sia = igb[g * 64 + c], sib = igb[g * 64 + c + 32];
            float sha = hgb[g * 64 + c], shb = hgb[g * 64 + c + 32];
            const float* r3 = sb3 + n * 64;
            const float* r4 = sb4 + n * 64;
            const float* hr = sh + n * 64;
            #pragma unroll 8
            for (int k = 0; k < 64; k++) {
                float v3 = r3[k], v4 = r4[k], vh = hr[k];
                const float* wi1 = sw + k * 64 + c;
                const float* wi2 = sw + (64 + k) * 64 + c;
                const float* wh  = sw + 8192 + k * 64 + c;
                sia += v3 * wi1[0];  sib += v3 * wi1[32];
                sia += v4 * wi2[0];  sib += v4 * wi2[32];
                sha += vh * wh[0];   shb += vh * wh[32];
            }
            int e0 = n * 64 + c, e1 = e0 + 32;
            if (g == 0) {
                sb1[e0] = sigmoidf_(sia + sha);
                sb1[e1] = sigmoidf_(sib + shb);
            } else if (g == 1) {
                sb2[e0] = sigmoidf_(sia + sha);
                sb2[e1] = sigmoidf_(sib + shb);
            } else {
                float ng0 = tanhf(sia + sb1[e0] * sha);
                float ng1 = tanhf(sib + sb1[e1] * shb);
                sb5[e0] = ng0 + sb2[e0] * (sh[e0] - ng0);
                sb5[e1] = ng1 + sb2[e1] * (sh[e1] - ng1);
            }
        }
        __syncthreads();
    }

    if (tid == 0) {
        int m = 0;
        for (int s = 0; s < SS; s++) m += mask[b * SS + s];
        s_last = m - 1;
    }
    for (int e = tid; e < SS * HH; e += 256) {
        int s = e >> 6, c = e & 63;
        sb3[e] = sb5[alias_inputs[b * SS + s] * 64 + c];
    }
    for (int e = tid; e < 4096; e += 256) sw[e] = fc2w[e];
    __syncthreads();

    if (tid < 64) {
        int c = tid;
        float q = fc1b[c];
        const float* htr = sb3 + s_last * 64;
        #pragma unroll 8
        for (int k = 0; k < 64; k++) q += htr[k] * fc1w[k * 64 + c];
        sq1[c] = q;
    }
    __syncthreads();

    for (int p = tid; p < SS * 32; p += 256) {
        int s = p >> 5, c = p & 31;
        float qa = fc2b[c], qb = fc2b[c + 32];
        const float* sr = sb3 + s * 64;
        #pragma unroll 8
        for (int k = 0; k < 64; k++) {
            float sv = sr[k];
            const float* w = sw + k * 64 + c;
            qa += sv * w[0]; qb += sv * w[32];
        }
        int e0 = s * 64 + c, e1 = e0 + 32;
        sb4[e0] = sigmoidf_(sq1[c] + qa) * fc3w[c];
        sb4[e1] = sigmoidf_(sq1[c + 32] + qb) * fc3w[c + 32];
    }
    __syncthreads();

    if (tid < SS) {
        float al = 0.0f;
        #pragma unroll 8
        for (int c = 0; c < 64; c++) al += sb4[tid * 64 + c];
        salpha[tid] = al * (float)mask[b * SS + tid];
    }
    __syncthreads();

    if (tid < 64) {
        float a = 0.0f;
        #pragma unroll 5
        for (int s = 0; s < SS; s++) a += salpha[s] * sb3[s * 64 + tid];
        g_a[b * 64 + tid] = a;
    }
}

// ===========================================================================
// Phase 2: mma.sync bf16 split-precision GEMM (portable sm_80+ path; runs on
// the HMMA pipe on sm_103).
//   out[b][v] = dot(a[b,:], emb[1+v,:])
//   fp32 x = hi + lo (bf16); out = Ahi*Ehi + Ahi*Elo + Alo*Ehi
// CTA tile: M=128 x N=128, 256 threads (8 warps as 2x4), warp tile 64x32,
// fragments m16n8k16, K=64 per product, 3 products into same fp32 C frags.
// ===========================================================================

#define EPITCH 72                  // bf16 elems per smem row (144B, 4-bank skew)
#define TILE_BYTES (128 * EPITCH * 2)   // 18432
#define OFF_AHI 0
#define OFF_ALO TILE_BYTES
#define OFF_EHI (2 * TILE_BYTES)
#define OFF_ELO (3 * TILE_BYTES)
#define GT_BYTES (4 * TILE_BYTES)       // 73728

static __device__ __forceinline__ uint32_t smem_u32(const void* p) {
    uint32_t a;
    asm("{ .reg .u64 t; cvta.to.shared.u64 t, %1; cvt.u32.u64 %0, t; }"
        : "=r"(a) : "l"(p));
    return a;
}

static __device__ __forceinline__ void ldsm_x4(
    uint32_t& r0, uint32_t& r1, uint32_t& r2, uint32_t& r3, uint32_t addr)
{
    asm volatile("ldmatrix.sync.aligned.m8n8.x4.shared.b16 {%0,%1,%2,%3}, [%4];"
                 : "=r"(r0), "=r"(r1), "=r"(r2), "=r"(r3) : "r"(addr));
}

static __device__ __forceinline__ void ldsm_x2(
    uint32_t& r0, uint32_t& r1, uint32_t addr)
{
    asm volatile("ldmatrix.sync.aligned.m8n8.x2.shared.b16 {%0,%1}, [%2];"
                 : "=r"(r0), "=r"(r1) : "r"(addr));
}

static __device__ __forceinline__ void mma_bf16(
    float* c, const uint32_t* a, const uint32_t* b)
{
    asm volatile(
        "mma.sync.aligned.m16n8k16.row.col.f32.bf16.bf16.f32 "
        "{%0,%1,%2,%3}, {%4,%5,%6,%7}, {%8,%9}, {%0,%1,%2,%3};"
        : "+f"(c[0]), "+f"(c[1]), "+f"(c[2]), "+f"(c[3])
        : "r"(a[0]), "r"(a[1]), "r"(a[2]), "r"(a[3]), "r"(b[0]), "r"(b[1]));
}

__global__ void __launch_bounds__(256, 2) gemm_mma_kernel(
    const float* __restrict__ emb, float* __restrict__ out)
{
    extern __shared__ char smc[];
    const uint32_t smb = smem_u32(smc);
    const int tid = threadIdx.x;
    const int wid = tid >> 5;
    const int lid = tid & 31;
    const int warp_m = wid & 1;        // 0..1  -> 64-row block
    const int warp_n = wid >> 1;       // 0..3  -> 32-col block
    const int b0 = blockIdx.x * 128;   // batch tile (fast dim -> emb L2 reuse)
    const int v0 = blockIdx.y * 128;   // vocab tile

    __nv_bfloat16* saHi = (__nv_bfloat16*)(smc + OFF_AHI);
    __nv_bfloat16* saLo = (__nv_bfloat16*)(smc + OFF_ALO);
    __nv_bfloat16* seHi = (__nv_bfloat16*)(smc + OFF_EHI);
    __nv_bfloat16* seLo = (__nv_bfloat16*)(smc + OFF_ELO);

    // ---- Stage A tile: a[b0+m][k] -> hi/lo bf16, padded rows
    for (int idx = tid; idx < 128 * 16; idx += 256) {
        int m = idx >> 4, q = idx & 15;
        float4 v = *(const float4*)&g_a[(b0 + m) * 64 + q * 4];
        __nv_bfloat16 h0 = __float2bfloat16(v.x);
        __nv_bfloat16 h1 = __float2bfloat16(v.y);
        __nv_bfloat16 h2 = __float2bfloat16(v.z);
        __nv_bfloat16 h3 = __float2bfloat16(v.w);
        int o = m * EPITCH + q * 4;
        *(__nv_bfloat162*)&saHi[o]     = __nv_bfloat162(h0, h1);
        *(__nv_bfloat162*)&saHi[o + 2] = __nv_bfloat162(h2, h3);
        *(__nv_bfloat162*)&saLo[o] =
            __nv_bfloat162(__float2bfloat16(v.x - __bfloat162float(h0)),
                           __float2bfloat16(v.y - __bfloat162float(h1)));
        *(__nv_bfloat162*)&saLo[o + 2] =
            __nv_bfloat162(__float2bfloat16(v.z - __bfloat162float(h2)),
                           __float2bfloat16(v.w - __bfloat162float(h3)));
    }
    // ---- Stage E tile: emb[1+v0+vv][k] -> hi/lo bf16 (zero beyond VOUT)
    for (int idx = tid; idx < 128 * 16; idx += 256) {
        int vv = idx >> 4, q = idx & 15;
        float4 v = make_float4(0.f, 0.f, 0.f, 0.f);
        if (v0 + vv < VOUT)
            v = *(const float4*)&emb[(size_t)(1 + v0 + vv) * 64 + q * 4];
        __nv_bfloat16 h0 = __float2bfloat16(v.x);
        __nv_bfloat16 h1 = __float2bfloat16(v.y);
        __nv_bfloat16 h2 = __float2bfloat16(v.z);
        __nv_bfloat16 h3 = __float2bfloat16(v.w);
        int o = vv * EPITCH + q * 4;
        *(__nv_bfloat162*)&seHi[o]     = __nv_bfloat162(h0, h1);
        *(__nv_bfloat162*)&seHi[o + 2] = __nv_bfloat162(h2, h3);
        *(__nv_bfloat162*)&seLo[o] =
            __nv_bfloat162(__float2bfloat16(v.x - __bfloat162float(h0)),
                           __float2bfloat16(v.y - __bfloat162float(h1)));
        *(__nv_bfloat162*)&seLo[o + 2] =
            __nv_bfloat162(__float2bfloat16(v.z - __bfloat162float(h2)),
                           __float2bfloat16(v.w - __bfloat162float(h3)));
    }
    __syncthreads();

    // ldmatrix lane address components
    const int a_row = (lid & 7) + ((lid >> 3) & 1) * 8;   // + m_frag*16
    const int a_kc  = ((lid >> 4) & 1) * 8;               // + kstep*16
    const int lb    = lid & 15;
    const int b_row = lb & 7;                             // + n_frag*8
    const int b_kc  = (lb >> 3) * 8;                      // + kstep*16

    const uint32_t aoff = ((warp_m * 64 + a_row) * EPITCH + a_kc) * 2;
    const uint32_t boff = ((warp_n * 32 + b_row) * EPITCH + b_kc) * 2;

    float c[4][4][4];
    #pragma unroll
    for (int i = 0; i < 4; i++)
        #pragma unroll
        for (int j = 0; j < 4; j++)
            #pragma unroll
            for (int q = 0; q < 4; q++) c[i][j][q] = 0.0f;

    // 3 products: (Ahi,Ehi), (Ahi,Elo), (Alo,Ehi)
    const uint32_t aTile[3] = { OFF_AHI, OFF_AHI, OFF_ALO };
    const uint32_t eTile[3] = { OFF_EHI, OFF_ELO, OFF_EHI };

    #pragma unroll
    for (int p = 0; p < 3; p++) {
        const uint32_t abase = smb + aTile[p] + aoff;
        const uint32_t bbase = smb + eTile[p] + boff;
        #pragma unroll
        for (int ks = 0; ks < 4; ks++) {
            uint32_t af[4][4], bf[4][2];
            #pragma unroll
            for (int mf = 0; mf < 4; mf++)
                ldsm_x4(af[mf][0], af[mf][1], af[mf][2], af[mf][3],
                        abase + mf * 16 * EPITCH * 2 + ks * 32);
            #pragma unroll
            for (int nf = 0; nf < 4; nf++)
                ldsm_x2(bf[nf][0], bf[nf][1],
                        bbase + nf * 8 * EPITCH * 2 + ks * 32);
            #pragma unroll
            for (int mf = 0; mf < 4; mf++)
                #pragma unroll
                for (int nf = 0; nf < 4; nf++)
                    mma_bf16(c[mf][nf], af[mf], bf[nf]);
        }
    }

    // ---- Epilogue: direct stores (quad-lane -> 8 consecutive cols = 32B)
    const int rbase = b0 + warp_m * 64 + (lid >> 2);
    const int cbase = v0 + warp_n * 32 + (lid & 3) * 2;
    #pragma unroll
    for (int mf = 0; mf < 4; mf++) {
        #pragma unroll
        for (int nf = 0; nf < 4; nf++) {
            int col = cbase + nf * 8;
            float* r0p = out + (size_t)(rbase + mf * 16) * VOUT;
            float* r1p = r0p + (size_t)8 * VOUT;
            if (col < VOUT)     { r0p[col] = c[mf][nf][0]; r1p[col] = c[mf][nf][2]; }
            if (col + 1 < VOUT) { r0p[col + 1] = c[mf][nf][1]; r1p[col + 1] = c[mf][nf][3]; }
        }
    }
}

// ===========================================================================
extern "C" void kernel_launch(void* const* d_in, const int* in_sizes, int n_in,
                              void* d_out, int out_size)
{
    const int*   alias_inputs = (const int*)  d_in[0];
    const float* ain   = (const float*)d_in[1];
    const float* aou   = (const float*)d_in[2];
    const int*   items = (const int*)  d_in[3];
    const int*   mask  = (const int*)  d_in[4];
    /* d_in[5] edge_index unused */
    const float* emb   = (const float*)d_in[6];
    const float* einw  = (const float*)d_in[7];
    const float* einb  = (const float*)d_in[8];
    const float* eouw  = (const float*)d_in[9];
    const float* eoub  = (const float*)d_in[10];
    const float* biah  = (const float*)d_in[11];
    const float* boah  = (const float*)d_in[12];
    const float* igw   = (const float*)d_in[13];
    const float* igb   = (const float*)d_in[14];
    const float* hgw   = (const float*)d_in[15];
    const float* hgb   = (const float*)d_in[16];
    const float* fc1w  = (const float*)d_in[17];
    const float* fc1b  = (const float*)d_in[18];
    const float* fc2w  = (const float*)d_in[19];
    const float* fc2b  = (const float*)d_in[20];
    const float* fc3w  = (const float*)d_in[21];
    float* out = (float*)d_out;

    cudaFuncSetAttribute(session_kernel,
                         cudaFuncAttributeMaxDynamicSharedMemorySize,
                         SM1_FLOATS * 4);
    cudaFuncSetAttribute(gemm_mma_kernel,
                         cudaFuncAttributeMaxDynamicSharedMemorySize,
                         GT_BYTES);

    session_kernel<<<BATCH, 256, SM1_FLOATS * 4>>>(
        alias_inputs, ain, aou, items, mask, emb,
        einw, einb, eouw, eoub, biah, boah,
        igw, igb, hgw, hgb, fc1w, fc1b, fc2w, fc2b, fc3w);

    dim3 grid(8, (VOUT + 127) / 128, 1);   // x = batch-tile fast -> emb L2 reuse
    gemm_mma_kernel<<<grid, 256, GT_BYTES>>>(emb, out);
}

// round 4
// speedup vs baseline: 1.6369x; 1.1343x over previous
#include <cuda_runtime.h>
#include <cuda_bf16.h>
#include <math.h>
#include <stdint.h>

// Problem constants
#define BATCH 1024
#define NN 50
#define SS 50
#define HH 64
#define VOCAB 200000
#define VOUT 199999   // V-1 output columns

// Scratch for session embeddings a[B,H]
__device__ float g_a[BATCH * HH];

__device__ __forceinline__ float sigmoidf_(float x) {
    return 1.0f / (1.0f + expf(-x));
}

// ===========================================================================
// Phase 1: per-session GGNN cell + attention readout -> g_a
// smem (floats): sh 0 | sb1 3200 | sb2 6400 | sb3 9600 | sb4 12800
//                sb5 16000 | sw 19200 (6144) | sq1 25344 | salpha 25408
// total 25472 floats = 101888 B  -> 2 CTAs/SM
// ===========================================================================
#define SM1_FLOATS 25472

__global__ void __launch_bounds__(256, 2) session_kernel(
    const int* __restrict__ alias_inputs, const float* __restrict__ ain,
    const float* __restrict__ aou, const int* __restrict__ items,
    const int* __restrict__ mask, const float* __restrict__ emb,
    const float* __restrict__ einw, const float* __restrict__ einb,
    const float* __restrict__ eouw, const float* __restrict__ eoub,
    const float* __restrict__ biah, const float* __restrict__ boah,
    const float* __restrict__ igw, const float* __restrict__ igb,
    const float* __restrict__ hgw, const float* __restrict__ hgb,
    const float* __restrict__ fc1w, const float* __restrict__ fc1b,
    const float* __restrict__ fc2w, const float* __restrict__ fc2b,
    const float* __restrict__ fc3w)
{
    extern __shared__ float sm[];
    float* sh  = sm;
    float* sb1 = sm + 3200;
    float* sb2 = sm + 6400;
    float* sb3 = sm + 9600;
    float* sb4 = sm + 12800;
    float* sb5 = sm + 16000;
    float* sw  = sm + 19200;        // 6144 floats
    float* sq1 = sm + 25344;
    float* salpha = sm + 25408;
    __shared__ int s_last;

    const int b = blockIdx.x;
    const int tid = threadIdx.x;

    // Gather h = emb[items]; stage ein_w
    for (int e = tid; e < 4096; e += 256) sw[e] = einw[e];
    for (int e = tid; e < NN * HH; e += 256) {
        int n = e >> 6, c = e & 63;
        sh[e] = emb[(size_t)items[b * NN + n] * HH + c];
    }
    __syncthreads();

    // t1 = h @ ein_w + ein_b  (adjacent-col float2 microtile)
    for (int p = tid; p < NN * 32; p += 256) {
        int n = p >> 5, c2 = (p & 31) * 2;
        float2 acc = *(const float2*)&einb[c2];
        const float* hr = sh + n * 64;
        #pragma unroll 8
        for (int k = 0; k < 64; k++) {
            float hv = hr[k];
            float2 w = *(const float2*)&sw[k * 64 + c2];
            acc.x += hv * w.x; acc.y += hv * w.y;
        }
        *(float2*)&sb1[n * 64 + c2] = acc;
    }
    __syncthreads();
    // stage eou_w, compute t2
    for (int e = tid; e < 4096; e += 256) sw[e] = eouw[e];
    __syncthreads();
    for (int p = tid; p < NN * 32; p += 256) {
        int n = p >> 5, c2 = (p & 31) * 2;
        float2 acc = *(const float2*)&eoub[c2];
        const float* hr = sh + n * 64;
        #pragma unroll 8
        for (int k = 0; k < 64; k++) {
            float hv = hr[k];
            float2 w = *(const float2*)&sw[k * 64 + c2];
            acc.x += hv * w.x; acc.y += hv * w.y;
        }
        *(float2*)&sb2[n * 64 + c2] = acc;
    }
    __syncthreads();

    // input_in = ain @ t1 + b_iah -> sb3 ; input_out = aou @ t2 + b_oah -> sb4
    for (int p = tid; p < NN * 32; p += 256) {
        int n = p >> 5, c2 = (p & 31) * 2;
        float2 a1 = *(const float2*)&biah[c2];
        float2 a2 = *(const float2*)&boah[c2];
        const float* ar = ain + (size_t)b * (NN * NN) + n * NN;
        const float* br = aou + (size_t)b * (NN * NN) + n * NN;
        #pragma unroll 5
        for (int j = 0; j < NN; j++) {
            float av = ar[j], bv = br[j];
            float2 t1 = *(const float2*)&sb1[j * 64 + c2];
            float2 t2 = *(const float2*)&sb2[j * 64 + c2];
            a1.x += av * t1.x; a1.y += av * t1.y;
            a2.x += bv * t2.x; a2.y += bv * t2.y;
        }
        *(float2*)&sb3[n * 64 + c2] = a1;
        *(float2*)&sb4[n * 64 + c2] = a2;
    }
    __syncthreads();

    // GRU gates: 3 gates x 2 half-col chunks of 32 cols
    for (int g = 0; g < 3; g++) {
        for (int hf = 0; hf < 2; hf++) {
            int gcol = g * 64 + hf * 32;
            // stage igw rows 0..127 x 32 cols -> sw[0..4095]
            for (int e = tid; e < 4096; e += 256) {
                int k = e >> 5, cc = e & 31;
                sw[e] = igw[k * 192 + gcol + cc];
            }
            // stage hgw rows 0..63 x 32 cols -> sw[4096..6143]
            for (int e = tid; e < 2048; e += 256) {
                int k = e >> 5, cc = e & 31;
                sw[4096 + e] = hgw[k * 192 + gcol + cc];
            }
            __syncthreads();

            for (int p = tid; p < NN * 16; p += 256) {
                int n = p >> 4, cc2 = (p & 15) * 2;
                float2 si = *(const float2*)&igb[gcol + cc2];
                float2 shc = *(const float2*)&hgb[gcol + cc2];
                const float* r3 = sb3 + n * 64;
                const float* r4 = sb4 + n * 64;
                const float* hr = sh + n * 64;
                #pragma unroll 8
                for (int k = 0; k < 64; k++) {
                    float v3 = r3[k], v4 = r4[k], vh = hr[k];
                    float2 w1 = *(const float2*)&sw[k * 32 + cc2];
                    float2 w2 = *(const float2*)&sw[(64 + k) * 32 + cc2];
                    float2 wh = *(const float2*)&sw[4096 + k * 32 + cc2];
                    si.x += v3 * w1.x + v4 * w2.x;
                    si.y += v3 * w1.y + v4 * w2.y;
                    shc.x += vh * wh.x;
                    shc.y += vh * wh.y;
                }
                int e0 = n * 64 + hf * 32 + cc2;
                if (g == 0) {
                    sb1[e0]     = sigmoidf_(si.x + shc.x);
                    sb1[e0 + 1] = sigmoidf_(si.y + shc.y);
                } else if (g == 1) {
                    sb2[e0]     = sigmoidf_(si.x + shc.x);
                    sb2[e0 + 1] = sigmoidf_(si.y + shc.y);
                } else {
                    float ng0 = tanhf(si.x + sb1[e0] * shc.x);
                    float ng1 = tanhf(si.y + sb1[e0 + 1] * shc.y);
                    sb5[e0]     = ng0 + sb2[e0] * (sh[e0] - ng0);
                    sb5[e0 + 1] = ng1 + sb2[e0 + 1] * (sh[e0 + 1] - ng1);
                }
            }
            __syncthreads();
        }
    }

    // ---- attention readout, h_final = sb5 ----
    if (tid == 0) {
        int m = 0;
        for (int s = 0; s < SS; s++) m += mask[b * SS + s];
        s_last = m - 1;
    }
    for (int e = tid; e < SS * HH; e += 256) {
        int s = e >> 6, c = e & 63;
        sb3[e] = sb5[alias_inputs[b * SS + s] * 64 + c];
    }
    for (int e = tid; e < 4096; e += 256) sw[e] = fc2w[e];
    __syncthreads();

    if (tid < 64) {
        int c = tid;
        float q = fc1b[c];
        const float* htr = sb3 + s_last * 64;
        #pragma unroll 8
        for (int k = 0; k < 64; k++) q += htr[k] * fc1w[k * 64 + c];
        sq1[c] = q;
    }
    __syncthreads();

    for (int p = tid; p < SS * 32; p += 256) {
        int s = p >> 5, c2 = (p & 31) * 2;
        float2 q = *(const float2*)&fc2b[c2];
        const float* sr = sb3 + s * 64;
        #pragma unroll 8
        for (int k = 0; k < 64; k++) {
            float sv = sr[k];
            float2 w = *(const float2*)&sw[k * 64 + c2];
            q.x += sv * w.x; q.y += sv * w.y;
        }
        int e0 = s * 64 + c2;
        sb4[e0]     = sigmoidf_(sq1[c2] + q.x) * fc3w[c2];
        sb4[e0 + 1] = sigmoidf_(sq1[c2 + 1] + q.y) * fc3w[c2 + 1];
    }
    __syncthreads();

    if (tid < SS) {
        float al = 0.0f;
        #pragma unroll 8
        for (int c = 0; c < 64; c++) al += sb4[tid * 64 + c];
        salpha[tid] = al * (float)mask[b * SS + tid];
    }
    __syncthreads();

    if (tid < 64) {
        float a = 0.0f;
        #pragma unroll 5
        for (int s = 0; s < SS; s++) a += salpha[s] * sb3[s * 64 + tid];
        g_a[b * 64 + tid] = a;
    }
}

// ===========================================================================
// Phase 2: mma.sync bf16 split-precision GEMM with fragment reuse
//   out = Ahi*Ehi + Ahi*Elo + Alo*Ehi
// CTA tile 128x128, 256 thr (8 warps 2x4), warp tile 64x32, m16n8k16.
// Per kstep: A frags loaded ONCE (8 ldsm.x4), B frags via ldsm.x4 in two
// nf-pair passes (register pressure), 48 MMAs issued back-to-back.
// ===========================================================================

#define EPITCH 72
#define TILE_BYTES (128 * EPITCH * 2)
#define OFF_AHI 0
#define OFF_ALO TILE_BYTES
#define OFF_EHI (2 * TILE_BYTES)
#define OFF_ELO (3 * TILE_BYTES)
#define GT_BYTES (4 * TILE_BYTES)

static __device__ __forceinline__ uint32_t smem_u32(const void* p) {
    uint32_t a;
    asm("{ .reg .u64 t; cvta.to.shared.u64 t, %1; cvt.u32.u64 %0, t; }"
        : "=r"(a) : "l"(p));
    return a;
}

static __device__ __forceinline__ void ldsm_x4(
    uint32_t& r0, uint32_t& r1, uint32_t& r2, uint32_t& r3, uint32_t addr)
{
    asm volatile("ldmatrix.sync.aligned.m8n8.x4.shared.b16 {%0,%1,%2,%3}, [%4];"
                 : "=r"(r0), "=r"(r1), "=r"(r2), "=r"(r3) : "r"(addr));
}

static __device__ __forceinline__ void mma_bf16(
    float* c, const uint32_t* a, const uint32_t* b)
{
    asm volatile(
        "mma.sync.aligned.m16n8k16.row.col.f32.bf16.bf16.f32 "
        "{%0,%1,%2,%3}, {%4,%5,%6,%7}, {%8,%9}, {%0,%1,%2,%3};"
        : "+f"(c[0]), "+f"(c[1]), "+f"(c[2]), "+f"(c[3])
        : "r"(a[0]), "r"(a[1]), "r"(a[2]), "r"(a[3]), "r"(b[0]), "r"(b[1]));
}

__global__ void __launch_bounds__(256, 2) gemm_mma_kernel(
    const float* __restrict__ emb, float* __restrict__ out)
{
    extern __shared__ char smc[];
    const uint32_t smb = smem_u32(smc);
    const int tid = threadIdx.x;
    const int wid = tid >> 5;
    const int lid = tid & 31;
    const int warp_m = wid & 1;        // 0..1  -> 64-row block
    const int warp_n = wid >> 1;       // 0..3  -> 32-col block
    const int b0 = blockIdx.x * 128;   // batch tile (fast dim -> emb L2 reuse)
    const int v0 = blockIdx.y * 128;   // vocab tile

    __nv_bfloat16* saHi = (__nv_bfloat16*)(smc + OFF_AHI);
    __nv_bfloat16* saLo = (__nv_bfloat16*)(smc + OFF_ALO);
    __nv_bfloat16* seHi = (__nv_bfloat16*)(smc + OFF_EHI);
    __nv_bfloat16* seLo = (__nv_bfloat16*)(smc + OFF_ELO);

    // ---- Stage A tile: a[b0+m][k] -> hi/lo bf16, padded rows
    for (int idx = tid; idx < 128 * 16; idx += 256) {
        int m = idx >> 4, q = idx & 15;
        float4 v = *(const float4*)&g_a[(b0 + m) * 64 + q * 4];
        __nv_bfloat16 h0 = __float2bfloat16(v.x);
        __nv_bfloat16 h1 = __float2bfloat16(v.y);
        __nv_bfloat16 h2 = __float2bfloat16(v.z);
        __nv_bfloat16 h3 = __float2bfloat16(v.w);
        int o = m * EPITCH + q * 4;
        *(__nv_bfloat162*)&saHi[o]     = __nv_bfloat162(h0, h1);
        *(__nv_bfloat162*)&saHi[o + 2] = __nv_bfloat162(h2, h3);
        *(__nv_bfloat162*)&saLo[o] =
            __nv_bfloat162(__float2bfloat16(v.x - __bfloat162float(h0)),
                           __float2bfloat16(v.y - __bfloat162float(h1)));
        *(__nv_bfloat162*)&saLo[o + 2] =
            __nv_bfloat162(__float2bfloat16(v.z - __bfloat162float(h2)),
                           __float2bfloat16(v.w - __bfloat162float(h3)));
    }
    // ---- Stage E tile: emb[1+v0+vv][k] -> hi/lo bf16 (zero beyond VOUT)
    for (int idx = tid; idx < 128 * 16; idx += 256) {
        int vv = idx >> 4, q = idx & 15;
        float4 v = make_float4(0.f, 0.f, 0.f, 0.f);
        if (v0 + vv < VOUT)
            v = *(const float4*)&emb[(size_t)(1 + v0 + vv) * 64 + q * 4];
        __nv_bfloat16 h0 = __float2bfloat16(v.x);
        __nv_bfloat16 h1 = __float2bfloat16(v.y);
        __nv_bfloat16 h2 = __float2bfloat16(v.z);
        __nv_bfloat16 h3 = __float2bfloat16(v.w);
        int o = vv * EPITCH + q * 4;
        *(__nv_bfloat162*)&seHi[o]     = __nv_bfloat162(h0, h1);
        *(__nv_bfloat162*)&seHi[o + 2] = __nv_bfloat162(h2, h3);
        *(__nv_bfloat162*)&seLo[o] =
            __nv_bfloat162(__float2bfloat16(v.x - __bfloat162float(h0)),
                           __float2bfloat16(v.y - __bfloat162float(h1)));
        *(__nv_bfloat162*)&seLo[o + 2] =
            __nv_bfloat162(__float2bfloat16(v.z - __bfloat162float(h2)),
                           __float2bfloat16(v.w - __bfloat162float(h3)));
    }
    __syncthreads();

    // ldmatrix lane address components
    // A (x4): lanes 0-7 rows 0-7 k0 | 8-15 rows 8-15 k0 | 16-23 rows 0-7 k8 | 24-31 rows 8-15 k8
    const int a_row = (lid & 7) + ((lid >> 3) & 1) * 8;
    const int a_kc  = ((lid >> 4) & 1) * 8;
    // B (x4): lanes 0-7 n0-7 k0 | 8-15 n0-7 k8 | 16-23 n8-15 k0 | 24-31 n8-15 k8
    const int b_row = (lid & 7) + ((lid >> 4) & 1) * 8;
    const int b_kc  = ((lid >> 3) & 1) * 8;

    const uint32_t aoff = ((warp_m * 64 + a_row) * EPITCH + a_kc) * 2;
    const uint32_t boff = ((warp_n * 32 + b_row) * EPITCH + b_kc) * 2;

    float c[4][4][4];
    #pragma unroll
    for (int i = 0; i < 4; i++)
        #pragma unroll
        for (int j = 0; j < 4; j++)
            #pragma unroll
            for (int q = 0; q < 4; q++) c[i][j][q] = 0.0f;

    const uint32_t aHiB = smb + OFF_AHI + aoff;
    const uint32_t aLoB = smb + OFF_ALO + aoff;
    const uint32_t eHiB = smb + OFF_EHI + boff;
    const uint32_t eLoB = smb + OFF_ELO + boff;

    #pragma unroll
    for (int ks = 0; ks < 4; ks++) {
        // A fragments once per kstep
        uint32_t ah[4][4], al[4][4];
        #pragma unroll
        for (int mf = 0; mf < 4; mf++) {
            ldsm_x4(ah[mf][0], ah[mf][1], ah[mf][2], ah[mf][3],
                    aHiB + mf * 16 * EPITCH * 2 + ks * 32);
            ldsm_x4(al[mf][0], al[mf][1], al[mf][2], al[mf][3],
                    aLoB + mf * 16 * EPITCH * 2 + ks * 32);
        }
        // B in two nf-pair passes (keeps live regs under the 128 cap)
        #pragma unroll
        for (int np = 0; np < 2; np++) {
            uint32_t bh[4], bl[4];   // {nf=2np: r0,r1} {nf=2np+1: r2,r3}
            ldsm_x4(bh[0], bh[1], bh[2], bh[3],
                    eHiB + np * 16 * EPITCH * 2 + ks * 32);
            ldsm_x4(bl[0], bl[1], bl[2], bl[3],
                    eLoB + np * 16 * EPITCH * 2 + ks * 32);
            #pragma unroll
            for (int h = 0; h < 2; h++) {
                int nf = np * 2 + h;
                #pragma unroll
                for (int mf = 0; mf < 4; mf++) {
                    mma_bf16(c[mf][nf], ah[mf], bh + 2 * h);
                    mma_bf16(c[mf][nf], ah[mf], bl + 2 * h);
                    mma_bf16(c[mf][nf], al[mf], bh + 2 * h);
                }
            }
        }
    }

    // ---- Epilogue: direct stores
    const int rbase = b0 + warp_m * 64 + (lid >> 2);
    const int cbase = v0 + warp_n * 32 + (lid & 3) * 2;
    #pragma unroll
    for (int mf = 0; mf < 4; mf++) {
        #pragma unroll
        for (int nf = 0; nf < 4; nf++) {
            int col = cbase + nf * 8;
            float* r0p = out + (size_t)(rbase + mf * 16) * VOUT;
            float* r1p = r0p + (size_t)8 * VOUT;
            if (col < VOUT)     { r0p[col] = c[mf][nf][0]; r1p[col] = c[mf][nf][2]; }
            if (col + 1 < VOUT) { r0p[col + 1] = c[mf][nf][1]; r1p[col + 1] = c[mf][nf][3]; }
        }
    }
}

// ===========================================================================
extern "C" void kernel_launch(void* const* d_in, const int* in_sizes, int n_in,
                              void* d_out, int out_size)
{
    const int*   alias_inputs = (const int*)  d_in[0];
    const float* ain   = (const float*)d_in[1];
    const float* aou   = (const float*)d_in[2];
    const int*   items = (const int*)  d_in[3];
    const int*   mask  = (const int*)  d_in[4];
    /* d_in[5] edge_index unused */
    const float* emb   = (const float*)d_in[6];
    const float* einw  = (const float*)d_in[7];
    const float* einb  = (const float*)d_in[8];
    const float* eouw  = (const float*)d_in[9];
    const float* eoub  = (const float*)d_in[10];
    const float* biah  = (const float*)d_in[11];
    const float* boah  = (const float*)d_in[12];
    const float* igw   = (const float*)d_in[13];
    const float* igb   = (const float*)d_in[14];
    const float* hgw   = (const float*)d_in[15];
    const float* hgb   = (const float*)d_in[16];
    const float* fc1w  = (const float*)d_in[17];
    const float* fc1b  = (const float*)d_in[18];
    const float* fc2w  = (const float*)d_in[19];
    const float* fc2b  = (const float*)d_in[20];
    const float* fc3w  = (const float*)d_in[21];
    float* out = (float*)d_out;

    cudaFuncSetAttribute(session_kernel,
                         cudaFuncAttributeMaxDynamicSharedMemorySize,
                         SM1_FLOATS * 4);
    cudaFuncSetAttribute(gemm_mma_kernel,
                         cudaFuncAttributeMaxDynamicSharedMemorySize,
                         GT_BYTES);

    session_kernel<<<BATCH, 256, SM1_FLOATS * 4>>>(
        alias_inputs, ain, aou, items, mask, emb,
        einw, einb, eouw, eoub, biah, boah,
        igw, igb, hgw, hgb, fc1w, fc1b, fc2w, fc2b, fc3w);

    dim3 grid(8, (VOUT + 127) / 128, 1);   // x = batch-tile fast -> emb L2 reuse
    gemm_mma_kernel<<<grid, 256, GT_BYTES>>>(emb, out);
}

// round 6
// speedup vs baseline: 1.7093x; 1.0442x over previous
#include <cuda_runtime.h>
#include <cuda_bf16.h>
#include <math.h>
#include <stdint.h>

// Problem constants
#define BATCH 1024
#define NN 50
#define SS 50
#define HH 64
#define VOCAB 200000
#define VOUT 199999   // V-1 output columns

// Scratch for session embeddings a[B,H]
__device__ float g_a[BATCH * HH];

__device__ __forceinline__ float sigmoidf_(float x) {
    return 1.0f / (1.0f + expf(-x));
}

__device__ __forceinline__ void fma4_(float4& a, float s, const float4 w) {
    a.x += s * w.x; a.y += s * w.y; a.z += s * w.z; a.w += s * w.w;
}

// ===========================================================================
// Phase 1: per-session GGNN cell + attention readout -> g_a
// smem (floats): sh 0 | sb1 3200 | sb2 6400 | sb3 9600 | sb4 12800
//                sb5 16000 | sw 19200 (6144) | sq1 25344 | salpha 25408
// 25472 floats = 101888 B -> 2 CTAs/SM
// ===========================================================================
#define SM1_FLOATS 25472

__global__ void __launch_bounds__(256, 2) session_kernel(
    const int* __restrict__ alias_inputs, const float* __restrict__ ain,
    const float* __restrict__ aou, const int* __restrict__ items,
    const int* __restrict__ mask, const float* __restrict__ emb,
    const float* __restrict__ einw, const float* __restrict__ einb,
    const float* __restrict__ eouw, const float* __restrict__ eoub,
    const float* __restrict__ biah, const float* __restrict__ boah,
    const float* __restrict__ igw, const float* __restrict__ igb,
    const float* __restrict__ hgw, const float* __restrict__ hgb,
    const float* __restrict__ fc1w, const float* __restrict__ fc1b,
    const float* __restrict__ fc2w, const float* __restrict__ fc2b,
    const float* __restrict__ fc3w)
{
    extern __shared__ float sm[];
    float* sh  = sm;
    float* sb1 = sm + 3200;
    float* sb2 = sm + 6400;
    float* sb3 = sm + 9600;
    float* sb4 = sm + 12800;
    float* sb5 = sm + 16000;
    float* sw  = sm + 19200;        // 6144 floats
    float* sq1 = sm + 25344;
    float* salpha = sm + 25408;
    __shared__ int s_last;

    const int b = blockIdx.x;
    const int tid = threadIdx.x;

    // Gather h = emb[items]; stage ein_w
    for (int e = tid; e < 4096; e += 256) sw[e] = einw[e];
    for (int e = tid; e < NN * HH; e += 256) {
        int n = e >> 6, c = e & 63;
        sh[e] = emb[(size_t)items[b * NN + n] * HH + c];
    }
    __syncthreads();

    // t1 = h @ ein_w + ein_b   (8 cols / thread, float4 weight loads)
    for (int p = tid; p < NN * 8; p += 256) {
        int n = p >> 3, cg = (p & 7) * 8;
        float4 a0 = *(const float4*)&einb[cg];
        float4 a1 = *(const float4*)&einb[cg + 4];
        const float* hr = sh + n * 64;
        #pragma unroll 8
        for (int k = 0; k < 64; k++) {
            float hv = hr[k];
            fma4_(a0, hv, *(const float4*)&sw[k * 64 + cg]);
            fma4_(a1, hv, *(const float4*)&sw[k * 64 + cg + 4]);
        }
        *(float4*)&sb1[n * 64 + cg]     = a0;
        *(float4*)&sb1[n * 64 + cg + 4] = a1;
    }
    __syncthreads();
    // stage eou_w, compute t2
    for (int e = tid; e < 4096; e += 256) sw[e] = eouw[e];
    __syncthreads();
    for (int p = tid; p < NN * 8; p += 256) {
        int n = p >> 3, cg = (p & 7) * 8;
        float4 a0 = *(const float4*)&eoub[cg];
        float4 a1 = *(const float4*)&eoub[cg + 4];
        const float* hr = sh + n * 64;
        #pragma unroll 8
        for (int k = 0; k < 64; k++) {
            float hv = hr[k];
            fma4_(a0, hv, *(const float4*)&sw[k * 64 + cg]);
            fma4_(a1, hv, *(const float4*)&sw[k * 64 + cg + 4]);
        }
        *(float4*)&sb2[n * 64 + cg]     = a0;
        *(float4*)&sb2[n * 64 + cg + 4] = a1;
    }
    __syncthreads();

    // Stage adjacency into sw (ain 0..2499, aou 2500..4999)
    {
        const float* ainb = ain + (size_t)b * (NN * NN);
        const float* aoub = aou + (size_t)b * (NN * NN);
        for (int e = tid; e < NN * NN; e += 256) {
            sw[e]        = ainb[e];
            sw[2500 + e] = aoub[e];
        }
    }
    __syncthreads();

    // input_in = ain @ t1 + b_iah -> sb3 ; input_out = aou @ t2 + b_oah -> sb4
    for (int p = tid; p < NN * 8; p += 256) {
        int n = p >> 3, cg = (p & 7) * 8;
        float4 i0 = *(const float4*)&biah[cg];
        float4 i1 = *(const float4*)&biah[cg + 4];
        float4 o0 = *(const float4*)&boah[cg];
        float4 o1 = *(const float4*)&boah[cg + 4];
        const float* ar = sw + n * NN;
        const float* br = sw + 2500 + n * NN;
        #pragma unroll 5
        for (int j = 0; j < NN; j++) {
            float av = ar[j], bv = br[j];
            fma4_(i0, av, *(const float4*)&sb1[j * 64 + cg]);
            fma4_(i1, av, *(const float4*)&sb1[j * 64 + cg + 4]);
            fma4_(o0, bv, *(const float4*)&sb2[j * 64 + cg]);
            fma4_(o1, bv, *(const float4*)&sb2[j * 64 + cg + 4]);
        }
        *(float4*)&sb3[n * 64 + cg]     = i0;
        *(float4*)&sb3[n * 64 + cg + 4] = i1;
        *(float4*)&sb4[n * 64 + cg]     = o0;
        *(float4*)&sb4[n * 64 + cg + 4] = o1;
    }
    __syncthreads();

    // GRU gates: 3 gates x 2 half-col chunks of 32 cols
    for (int g = 0; g < 3; g++) {
        for (int hf = 0; hf < 2; hf++) {
            int gcol = g * 64 + hf * 32;
            for (int e = tid; e < 4096; e += 256) {
                int k = e >> 5, cc = e & 31;
                sw[e] = igw[k * 192 + gcol + cc];
            }
            for (int e = tid; e < 2048; e += 256) {
                int k = e >> 5, cc = e & 31;
                sw[4096 + e] = hgw[k * 192 + gcol + cc];
            }
            __syncthreads();

            if (tid < NN * 4) {
                int n = tid >> 2, cg = (tid & 3) * 8;
                float4 s0 = *(const float4*)&igb[gcol + cg];
                float4 s1 = *(const float4*)&igb[gcol + cg + 4];
                float4 h0 = *(const float4*)&hgb[gcol + cg];
                float4 h1 = *(const float4*)&hgb[gcol + cg + 4];
                const float* r3 = sb3 + n * 64;
                const float* r4 = sb4 + n * 64;
                const float* hr = sh + n * 64;
                #pragma unroll 8
                for (int k = 0; k < 64; k++) {
                    float v3 = r3[k], v4 = r4[k], vh = hr[k];
                    fma4_(s0, v3, *(const float4*)&sw[k * 32 + cg]);
                    fma4_(s1, v3, *(const float4*)&sw[k * 32 + cg + 4]);
                    fma4_(s0, v4, *(const float4*)&sw[(64 + k) * 32 + cg]);
                    fma4_(s1, v4, *(const float4*)&sw[(64 + k) * 32 + cg + 4]);
                    fma4_(h0, vh, *(const float4*)&sw[4096 + k * 32 + cg]);
                    fma4_(h1, vh, *(const float4*)&sw[4096 + k * 32 + cg + 4]);
                }
                int e0 = n * 64 + hf * 32 + cg;
                float siv[8] = {s0.x, s0.y, s0.z, s0.w, s1.x, s1.y, s1.z, s1.w};
                float shv[8] = {h0.x, h0.y, h0.z, h0.w, h1.x, h1.y, h1.z, h1.w};
                if (g == 0) {
                    #pragma unroll
                    for (int q = 0; q < 8; q++)
                        sb1[e0 + q] = sigmoidf_(siv[q] + shv[q]);
                } else if (g == 1) {
                    #pragma unroll
                    for (int q = 0; q < 8; q++)
                        sb2[e0 + q] = sigmoidf_(siv[q] + shv[q]);
                } else {
                    #pragma unroll
                    for (int q = 0; q < 8; q++) {
                        float ng = tanhf(siv[q] + sb1[e0 + q] * shv[q]);
                        sb5[e0 + q] = ng + sb2[e0 + q] * (sh[e0 + q] - ng);
                    }
                }
            }
            __syncthreads();
        }
    }

    // ---- attention readout, h_final = sb5 ----
    if (tid == 0) {
        int m = 0;
        for (int s = 0; s < SS; s++) m += mask[b * SS + s];
        s_last = m - 1;
    }
    for (int e = tid; e < SS * HH; e += 256) {
        int s = e >> 6, c = e & 63;
        sb3[e] = sb5[alias_inputs[b * SS + s] * 64 + c];
    }
    for (int e = tid; e < 4096; e += 256) sw[e] = fc2w[e];
    __syncthreads();

    if (tid < 64) {
        int c = tid;
        float q = fc1b[c];
        const float* htr = sb3 + s_last * 64;
        #pragma unroll 8
        for (int k = 0; k < 64; k++) q += htr[k] * fc1w[k * 64 + c];
        sq1[c] = q;
    }
    __syncthreads();

    // vals[s][c] = sigmoid(q1 + seq@fc2 + b) * fc3_w  -> sb4
    for (int p = tid; p < SS * 8; p += 256) {
        int s = p >> 3, cg = (p & 7) * 8;
        float4 q0 = *(const float4*)&fc2b[cg];
        float4 q1 = *(const float4*)&fc2b[cg + 4];
        const float* sr = sb3 + s * 64;
        #pragma unroll 8
        for (int k = 0; k < 64; k++) {
            float sv = sr[k];
            fma4_(q0, sv, *(const float4*)&sw[k * 64 + cg]);
            fma4_(q1, sv, *(const float4*)&sw[k * 64 + cg + 4]);
        }
        float qv[8] = {q0.x, q0.y, q0.z, q0.w, q1.x, q1.y, q1.z, q1.w};
        #pragma unroll
        for (int q = 0; q < 8; q++)
            sb4[s * 64 + cg + q] =
                sigmoidf_(sq1[cg + q] + qv[q]) * fc3w[cg + q];
    }
    __syncthreads();

    if (tid < SS) {
        float al = 0.0f;
        #pragma unroll 8
        for (int c = 0; c < 64; c++) al += sb4[tid * 64 + c];
        salpha[tid] = al * (float)mask[b * SS + tid];
    }
    __syncthreads();

    if (tid < 64) {
        float a = 0.0f;
        #pragma unroll 5
        for (int s = 0; s < SS; s++) a += salpha[s] * sb3[s * 64 + tid];
        g_a[b * 64 + tid] = a;
    }
}

// ===========================================================================
// Phase 2: mma.sync bf16 split-precision GEMM, cp.async-pipelined.
//   fp32 x = hi(trunc16) + lo;  out = Ahi*Ehi + Ahi*Elo + Alo*Ehi
// CTA tile 128x128, 256 thr (8 warps 2x4), warp tile 64x32, m16n8k16.
// A staged ONCE per CTA as bf16 hi/lo (ldmatrix). E kept fp32 in a double-
// buffered cp.async ring; B fragments split hi/lo in registers per use.
// Each CTA processes T_VTILES consecutive v-tiles.
// ===========================================================================

#define EPITCH 72                       // A bf16 row pitch (elems)
#define EP 68                           // E fp32 row pitch (floats, 16B mult)
#define OFF_AHI 0
#define OFF_ALO 18432                   // 128*72*2
#define OFF_E0  36864
#define OFF_E1  71680                   // +128*68*4 = 34816
#define GT_BYTES 106496
#define T_VTILES 4
#define NVTILES 1563                    // ceil(VOUT/128)

static __device__ __forceinline__ uint32_t smem_u32(const void* p) {
    uint32_t a;
    asm("{ .reg .u64 t; cvta.to.shared.u64 t, %1; cvt.u32.u64 %0, t; }"
        : "=r"(a) : "l"(p));
    return a;
}

static __device__ __forceinline__ void ldsm_x4(
    uint32_t& r0, uint32_t& r1, uint32_t& r2, uint32_t& r3, uint32_t addr)
{
    asm volatile("ldmatrix.sync.aligned.m8n8.x4.shared.b16 {%0,%1,%2,%3}, [%4];"
                 : "=r"(r0), "=r"(r1), "=r"(r2), "=r"(r3) : "r"(addr));
}

static __device__ __forceinline__ void mma_bf16(
    float* c, const uint32_t* a, const uint32_t* b)
{
    asm volatile(
        "mma.sync.aligned.m16n8k16.row.col.f32.bf16.bf16.f32 "
        "{%0,%1,%2,%3}, {%4,%5,%6,%7}, {%8,%9}, {%0,%1,%2,%3};"
        : "+f"(c[0]), "+f"(c[1]), "+f"(c[2]), "+f"(c[3])
        : "r"(a[0]), "r"(a[1]), "r"(a[2]), "r"(a[3]), "r"(b[0]), "r"(b[1]));
}

// hi = truncate-to-bf16 pair pack; lo = exact residual, RN to bf16 pair
static __device__ __forceinline__ uint32_t hi_pack(float x, float y) {
    return __byte_perm(__float_as_uint(x), __float_as_uint(y), 0x7632);
}
static __device__ __forceinline__ float lo_res(float x) {
    return x - __uint_as_float(__float_as_uint(x) & 0xFFFF0000u);
}
static __device__ __forceinline__ uint32_t lo_pack(float x, float y) {
    uint32_t r;
    asm("cvt.rn.bf16x2.f32 %0, %1, %2;" : "=r"(r)
        : "f"(lo_res(y)), "f"(lo_res(x)));   // low16 = cvt(x)
    return r;
}

#define CP_ASYNC16(dst, src) \
    asm volatile("cp.async.cg.shared.global [%0], [%1], 16;" \
                 :: "r"(dst), "l"(src))
#define CP_COMMIT()  asm volatile("cp.async.commit_group;" ::: "memory")
#define CP_WAIT(N)   asm volatile("cp.async.wait_group %0;" :: "n"(N) : "memory")

__global__ void __launch_bounds__(256, 2) gemm_mma_kernel(
    const float* __restrict__ emb, float* __restrict__ out)
{
    extern __shared__ char smc[];
    const uint32_t smb = smem_u32(smc);
    const int tid = threadIdx.x;
    const int wid = tid >> 5;
    const int lid = tid & 31;
    const int warp_m = wid & 1;        // 0..1  -> 64-row block
    const int warp_n = wid >> 1;       // 0..3  -> 32-col block
    const int b0 = blockIdx.x * 128;   // batch tile (fast dim -> emb L2 reuse)
    const int vt0 = blockIdx.y * T_VTILES;
    const int nv = (NVTILES - vt0 < T_VTILES) ? (NVTILES - vt0) : T_VTILES;

    __nv_bfloat16* saHi = (__nv_bfloat16*)(smc + OFF_AHI);
    __nv_bfloat16* saLo = (__nv_bfloat16*)(smc + OFF_ALO);

    // ---- Stage A tile once: a[b0+m][k] -> hi/lo bf16 (truncation split)
    for (int idx = tid; idx < 128 * 16; idx += 256) {
        int m = idx >> 4, q = idx & 15;
        float4 v = *(const float4*)&g_a[(b0 + m) * 64 + q * 4];
        int o = m * EPITCH + q * 4;
        *(uint32_t*)&saHi[o]     = hi_pack(v.x, v.y);
        *(uint32_t*)&saHi[o + 2] = hi_pack(v.z, v.w);
        *(uint32_t*)&saLo[o]     = lo_pack(v.x, v.y);
        *(uint32_t*)&saLo[o + 2] = lo_pack(v.z, v.w);
    }

    // ---- Prefetch E tile 0 (fp32, cp.async)
    {
        uint32_t dstb = smb + OFF_E0;
        #pragma unroll
        for (int i = 0; i < 8; i++) {
            int idx = tid + i * 256;
            int row = idx >> 4, c = (idx & 15) * 4;
            int grow = vt0 * 128 + row;
            if (grow < VOUT)
                CP_ASYNC16(dstb + (row * EP + c) * 4,
                           emb + (size_t)(1 + grow) * 64 + c);
        }
        CP_COMMIT();
    }

    // ldmatrix lane address components (A)
    const int a_row = (lid & 7) + ((lid >> 3) & 1) * 8;
    const int a_kc  = ((lid >> 4) & 1) * 8;
    const uint32_t aHiB = smb + OFF_AHI
        + ((warp_m * 64 + a_row) * EPITCH + a_kc) * 2;
    const uint32_t aLoB = smb + OFF_ALO
        + ((warp_m * 64 + a_row) * EPITCH + a_kc) * 2;

    // E per-thread fragment offset pieces
    const int e_r = lid >> 2;          // row within 8-row group
    const int e_q = (lid & 3) * 2;     // k pair offset

    for (int t = 0; t < nv; t++) {
        int vt = vt0 + t;
        // prefetch next tile into other buffer
        if (t + 1 < nv) {
            uint32_t dstb = smb + (((t + 1) & 1) ? OFF_E1 : OFF_E0);
            #pragma unroll
            for (int i = 0; i < 8; i++) {
                int idx = tid + i * 256;
                int row = idx >> 4, c = (idx & 15) * 4;
                int grow = (vt + 1) * 128 + row;
                if (grow < VOUT)
                    CP_ASYNC16(dstb + (row * EP + c) * 4,
                               emb + (size_t)(1 + grow) * 64 + c);
            }
            CP_COMMIT();
            CP_WAIT(1);
        } else {
            CP_WAIT(0);
        }
        __syncthreads();

        const float* Ebuf = (const float*)(smc + ((t & 1) ? OFF_E1 : OFF_E0));

        float c[4][4][4];
        #pragma unroll
        for (int i = 0; i < 4; i++)
            #pragma unroll
            for (int j = 0; j < 4; j++)
                #pragma unroll
                for (int q = 0; q < 4; q++) c[i][j][q] = 0.0f;

        #pragma unroll
        for (int ks = 0; ks < 4; ks++) {
            uint32_t ah[4][4], al[4][4];
            #pragma unroll
            for (int mf = 0; mf < 4; mf++) {
                ldsm_x4(ah[mf][0], ah[mf][1], ah[mf][2], ah[mf][3],
                        aHiB + mf * 16 * EPITCH * 2 + ks * 32);
                ldsm_x4(al[mf][0], al[mf][1], al[mf][2], al[mf][3],
                        aLoB + mf * 16 * EPITCH * 2 + ks * 32);
            }
            #pragma unroll
            for (int nf = 0; nf < 4; nf++) {
                const float* ep = Ebuf
                    + (warp_n * 32 + nf * 8 + e_r) * EP + ks * 16 + e_q;
                float2 u0 = *(const float2*)ep;
                float2 u1 = *(const float2*)(ep + 8);
                uint32_t bh[2], bl[2];
                bh[0] = hi_pack(u0.x, u0.y);
                bh[1] = hi_pack(u1.x, u1.y);
                bl[0] = lo_pack(u0.x, u0.y);
                bl[1] = lo_pack(u1.x, u1.y);
                #pragma unroll
                for (int mf = 0; mf < 4; mf++) {
                    mma_bf16(c[mf][nf], ah[mf], bh);
                    mma_bf16(c[mf][nf], ah[mf], bl);
                    mma_bf16(c[mf][nf], al[mf], bh);
                }
            }
        }

        // ---- Epilogue: direct stores
        const int v0 = vt * 128;
        const int rbase = b0 + warp_m * 64 + (lid >> 2);
        const int cbase = v0 + warp_n * 32 + (lid & 3) * 2;
        #pragma unroll
        for (int mf = 0; mf < 4; mf++) {
            #pragma unroll
            for (int nf = 0; nf < 4; nf++) {
                int col = cbase + nf * 8;
                float* r0p = out + (size_t)(rbase + mf * 16) * VOUT;
                float* r1p = r0p + (size_t)8 * VOUT;
                if (col < VOUT) {
                    r0p[col] = c[mf][nf][0]; r1p[col] = c[mf][nf][2];
                }
                if (col + 1 < VOUT) {
                    r0p[col + 1] = c[mf][nf][1]; r1p[col + 1] = c[mf][nf][3];
                }
            }
        }
        __syncthreads();   // buffer t&1 free for prefetch of t+2
    }
}

// ===========================================================================
extern "C" void kernel_launch(void* const* d_in, const int* in_sizes, int n_in,
                              void* d_out, int out_size)
{
    const int*   alias_inputs = (const int*)  d_in[0];
    const float* ain   = (const float*)d_in[1];
    const float* aou   = (const float*)d_in[2];
    const int*   items = (const int*)  d_in[3];
    const int*   mask  = (const int*)  d_in[4];
    /* d_in[5] edge_index unused */
    const float* emb   = (const float*)d_in[6];
    const float* einw  = (const float*)d_in[7];
    const float* einb  = (const float*)d_in[8];
    const float* eouw  = (const float*)d_in[9];
    const float* eoub  = (const float*)d_in[10];
    const float* biah  = (const float*)d_in[11];
    const float* boah  = (const float*)d_in[12];
    const float* igw   = (const float*)d_in[13];
    const float* igb   = (const float*)d_in[14];
    const float* hgw   = (const float*)d_in[15];
    const float* hgb   = (const float*)d_in[16];
    const float* fc1w  = (const float*)d_in[17];
    const float* fc1b  = (const float*)d_in[18];
    const float* fc2w  = (const float*)d_in[19];
    const float* fc2b  = (const float*)d_in[20];
    const float* fc3w  = (const float*)d_in[21];
    float* out = (float*)d_out;

    cudaFuncSetAttribute(session_kernel,
                         cudaFuncAttributeMaxDynamicSharedMemorySize,
                         SM1_FLOATS * 4);
    cudaFuncSetAttribute(gemm_mma_kernel,
                         cudaFuncAttributeMaxDynamicSharedMemorySize,
                         GT_BYTES);

    session_kernel<<<BATCH, 256, SM1_FLOATS * 4>>>(
        alias_inputs, ain, aou, items, mask, emb,
        einw, einb, eouw, eoub, biah, boah,
        igw, igb, hgw, hgb, fc1w, fc1b, fc2w, fc2b, fc3w);

    dim3 grid(8, (NVTILES + T_VTILES - 1) / T_VTILES, 1);
    gemm_mma_kernel<<<grid, 256, GT_BYTES>>>(emb, out);
}